// round 14
// baseline (speedup 1.0000x reference)
#include <cuda_runtime.h>
#include <cuda_fp16.h>
#include <cstdint>

#define NN 50000
#define EE 800000
#define KF 256
#define HH 8
#define WROWS 768   // [Wq;Wk;Wv]

#define XSPLIT 25088                   // row split (multiple of 128)
#define MT_A (XSPLIT / 128)            // 196 tiles in half A
#define MT_ALL ((NN + 127) / 128)      // 391
#define MT_B (MT_ALL - MT_A)           // 195

// ---------------------------------------------------------------------------
// Scratch (static device globals; no allocation anywhere)
// ---------------------------------------------------------------------------
__device__ __align__(16) __half g_q[(size_t)NN * 256];
__device__ __align__(16) __half g_k[(size_t)NN * 256];
__device__ __align__(16) float g_sum[NN * HH];
__device__ __align__(16) __half g_xh[(size_t)NN * KF];
__device__ __align__(16) __half g_wh[(size_t)WROWS * KF];

// ---------------------------------------------------------------------------
__device__ __forceinline__ uint32_t smem_u32(const void* p) {
    uint32_t a;
    asm("{ .reg .u64 t; cvta.to.shared.u64 t, %1; cvt.u32.u64 %0, t; }" : "=r"(a) : "l"(p));
    return a;
}
__device__ __forceinline__ void ldsm_x4(uint32_t* r, uint32_t addr) {
    asm volatile("ldmatrix.sync.aligned.m8n8.x4.shared.b16 {%0,%1,%2,%3}, [%4];"
                 : "=r"(r[0]), "=r"(r[1]), "=r"(r[2]), "=r"(r[3]) : "r"(addr));
}
__device__ __forceinline__ void mma_f16(float* c, const uint32_t* a, uint32_t b0, uint32_t b1) {
    asm volatile(
        "mma.sync.aligned.m16n8k16.row.col.f32.f16.f16.f32 "
        "{%0,%1,%2,%3}, {%4,%5,%6,%7}, {%8,%9}, {%0,%1,%2,%3};"
        : "+f"(c[0]), "+f"(c[1]), "+f"(c[2]), "+f"(c[3])
        : "r"(a[0]), "r"(a[1]), "r"(a[2]), "r"(a[3]), "r"(b0), "r"(b1));
}
__device__ __forceinline__ void cp_async16(uint32_t smem_addr, const void* gptr, uint32_t src_bytes) {
    asm volatile("cp.async.cg.shared.global [%0], [%1], 16, %2;"
                 :: "r"(smem_addr), "l"(gptr), "r"(src_bytes) : "memory");
}
#define CP_COMMIT() asm volatile("cp.async.commit_group;" ::: "memory")
#define CP_WAIT(n)  asm volatile("cp.async.wait_group %0;" :: "n"(n) : "memory")

// ---------------------------------------------------------------------------
// Conversion helpers
// ---------------------------------------------------------------------------
__device__ __forceinline__ void conv_group(const float* src, __half* dst, size_t off) {
    float4 v = *(const float4*)(src + off);
    __half2 p0 = __floats2half2_rn(v.x, v.y);
    __half2 p1 = __floats2half2_rn(v.z, v.w);
    uint2 u;
    u.x = *(uint32_t*)&p0; u.y = *(uint32_t*)&p1;
    *(uint2*)(dst + off) = u;
}

#define XA_GROUPS (XSPLIT * KF / 4)            // 1,605,632
#define XB_GROUPS ((NN - XSPLIT) * KF / 4)     // 1,594,368
#define WGROUPS (WROWS * KF / 4)               // 49,152
#define ZGROUPS (NN * HH / 4)                  // 100,000

// conv_AW: x rows [0, XSPLIT) + W concat + zero g_sum
__global__ void __launch_bounds__(256) conv_AW(
    const float* __restrict__ x,
    const float* __restrict__ Wq, const float* __restrict__ Wk, const float* __restrict__ Wv)
{
    int idx = blockIdx.x * 256 + threadIdx.x;
    if (idx < XA_GROUPS) {
        conv_group(x, g_xh, (size_t)idx * 4);
    } else if (idx < XA_GROUPS + WGROUPS) {
        size_t off = (size_t)(idx - XA_GROUPS) * 4;
        size_t row = off / KF;
        const float* Wm = (row < 256) ? Wq : (row < 512) ? Wk : Wv;
        const float* src = Wm - ((row < 256) ? 0 : (row < 512) ? 256 * KF : 512 * KF);
        conv_group(src, g_wh, off);
    } else {
        int z = idx - (XA_GROUPS + WGROUPS);
        if (z < ZGROUPS)
            *(float4*)(g_sum + (size_t)z * 4) = make_float4(0.f, 0.f, 0.f, 0.f);
    }
}

// conv_B: x rows [XSPLIT, NN)
__global__ void __launch_bounds__(256) conv_B(const float* __restrict__ x)
{
    int idx = blockIdx.x * 256 + threadIdx.x;
    if (idx < XB_GROUPS)
        conv_group(x, g_xh, (size_t)(XA_GROUPS + idx) * 4);
}

// ---------------------------------------------------------------------------
// Pipelined mma.sync QKV GEMM (fp16): C[N,768] = x @ W^T + b
// nt = ntBase + blockIdx.x : 0-1 -> g_q | 2-3 -> g_k | 4-5 -> out_v (staged)
// mT = mTBase + blockIdx.y
// BM=128, BN=128, BK=32; 8 warps; 5-stage cp.async pipeline (dist 4),
// ONE __syncthreads per slice. SMEM = 5*20480 = 102400.
// ---------------------------------------------------------------------------
#define NSTAGE 5
#define STAGE_BYTES 20480u   // A(128*40*2=10240) + B(10240)
#define B_OFF 10240u
#define SMEM_GEMM (NSTAGE * STAGE_BYTES)

extern __shared__ char dynsmem[];

__global__ void __launch_bounds__(256, 2) gemm_mma(
    int ntBase, int mTBase,
    const float* __restrict__ bq, const float* __restrict__ bk, const float* __restrict__ bv,
    float* __restrict__ out_v)
{
    const int t = threadIdx.x;
    const int wid = t >> 5;
    const int lane = t & 31;
    const int nt = ntBase + blockIdx.x;
    const int mT = mTBase + blockIdx.y;
    const bool isV = (nt >= 4);

    const int wm = (wid >> 1) * 32;
    const int wn = (wid & 1) * 64;

    const uint32_t sb = smem_u32(dynsmem);

    const int rA = (lane & 15);
    const int cA = (lane >> 4) << 3;
    const int rB = (lane & 7) + ((lane >> 4) << 3);
    const int cB = ((lane >> 3) & 1) << 3;

    uint32_t addrA[2], addrB[4];
#pragma unroll
    for (int mi = 0; mi < 2; mi++)
        addrA[mi] = sb + (uint32_t)(wm + mi * 16 + rA) * 80u + (uint32_t)cA * 2u;
#pragma unroll
    for (int nf4 = 0; nf4 < 4; nf4++)
        addrB[nf4] = sb + B_OFF + (uint32_t)(wn + nf4 * 16 + rB) * 80u + (uint32_t)cB * 2u;

    float acc[2][8][4];
#pragma unroll
    for (int mi = 0; mi < 2; mi++)
#pragma unroll
        for (int nf = 0; nf < 8; nf++)
#pragma unroll
            for (int i = 0; i < 4; i++) acc[mi][nf][i] = 0.f;

    const int lrow = t >> 1;
    const int lcg = (t & 1) * 16;
    const int growL = mT * 128 + lrow;
    const uint32_t aBytes = (growL < NN) ? 16u : 0u;
    const int brow = nt * 128 + lrow;

    const uint32_t dstA0 = sb + (uint32_t)lrow * 80u + (uint32_t)lcg * 2u;
    const uint32_t dstB0 = sb + B_OFF + (uint32_t)lrow * 80u + (uint32_t)lcg * 2u;

    auto issue = [&](int s) {
        if (s < 8) {
            const uint32_t st = (uint32_t)(s % NSTAGE) * STAGE_BYTES;
            const __half* ap = g_xh + (size_t)growL * KF + s * 32 + lcg;
            const __half* bp = g_wh + (size_t)brow * KF + s * 32 + lcg;
            cp_async16(dstA0 + st, ap, aBytes);
            cp_async16(dstA0 + st + 16, ap + 8, aBytes);
            cp_async16(dstB0 + st, bp, 16u);
            cp_async16(dstB0 + st + 16, bp + 8, 16u);
        }
        CP_COMMIT();
    };

    issue(0); issue(1); issue(2); issue(3);
#pragma unroll
    for (int s = 0; s < 8; s++) {
        CP_WAIT(3);
        __syncthreads();
        issue(s + 4);

        const uint32_t st = (uint32_t)(s % NSTAGE) * STAGE_BYTES;
#pragma unroll
        for (int kk = 0; kk < 2; kk++) {
            uint32_t afrag[2][4];
            ldsm_x4(afrag[0], addrA[0] + st + kk * 32);
            ldsm_x4(afrag[1], addrA[1] + st + kk * 32);
            uint32_t bfrag[4][4];
#pragma unroll
            for (int nf4 = 0; nf4 < 4; nf4++)
                ldsm_x4(bfrag[nf4], addrB[nf4] + st + kk * 32);
#pragma unroll
            for (int mi = 0; mi < 2; mi++)
#pragma unroll
                for (int nf = 0; nf < 8; nf++)
                    mma_f16(acc[mi][nf], afrag[mi],
                            bfrag[nf >> 1][(nf & 1) * 2],
                            bfrag[nf >> 1][(nf & 1) * 2 + 1]);
        }
    }

    const int g = lane >> 2, tg = lane & 3;

    if (!isV) {
        // ---- q/k epilogue: hoisted biases, direct half2 stores ----
        const bool isQ = (nt < 2);
        const float* bptr = isQ ? bq : bk;
        __half* dst = isQ ? g_q : g_k;
        const int colBase = (nt & 1) * 128;
        float bb[8][2];
#pragma unroll
        for (int nf = 0; nf < 8; nf++) {
            const int lc = colBase + wn + nf * 8 + tg * 2;
            bb[nf][0] = __ldg(bptr + lc);
            bb[nf][1] = __ldg(bptr + lc + 1);
        }
#pragma unroll
        for (int mi = 0; mi < 2; mi++) {
            const int r0 = wm + mi * 16 + g;
#pragma unroll
            for (int hh = 0; hh < 2; hh++) {
                const int gr = mT * 128 + r0 + hh * 8;
                if (gr >= NN) continue;
#pragma unroll
                for (int nf = 0; nf < 8; nf++) {
                    const int lc = colBase + wn + nf * 8 + tg * 2;
                    float v0 = acc[mi][nf][hh * 2]     + bb[nf][0];
                    float v1 = acc[mi][nf][hh * 2 + 1] + bb[nf][1];
                    __half2 p2 = __floats2half2_rn(v0, v1);
                    *(__half2*)(dst + (size_t)gr * 256 + lc) = p2;
                }
            }
        }
    } else {
        // ---- v epilogue: stage 64-row halves in SMEM, coalesced float4 out ----
        float* stg = (float*)dynsmem;
        const int wcBase = (nt - 4) * 128;
        float bb[8][2];
#pragma unroll
        for (int nf = 0; nf < 8; nf++) {
            const int c0 = wn + nf * 8 + tg * 2;
            bb[nf][0] = __ldg(bv + wcBase + c0);
            bb[nf][1] = __ldg(bv + wcBase + c0 + 1);
        }
#pragma unroll
        for (int hf = 0; hf < 2; hf++) {
            __syncthreads();
            if ((wm >> 6) == hf) {
#pragma unroll
                for (int mi = 0; mi < 2; mi++) {
#pragma unroll
                    for (int hh = 0; hh < 2; hh++) {
                        const int lr = (wm & 63) + mi * 16 + g + hh * 8;
#pragma unroll
                        for (int nf = 0; nf < 8; nf++) {
                            const int c0 = wn + nf * 8 + tg * 2;
                            float v0 = acc[mi][nf][hh * 2]     + bb[nf][0];
                            float v1 = acc[mi][nf][hh * 2 + 1] + bb[nf][1];
                            stg[lr * 132 + 4 * (c0 & 31) + (c0 >> 5)] = v0;
                            stg[lr * 132 + 4 * ((c0 + 1) & 31) + ((c0 + 1) >> 5)] = v1;
                        }
                    }
                }
            }
            __syncthreads();
#pragma unroll
            for (int it = 0; it < 8; it++) {
                const int idx = it * 256 + t;
                const int r = idx >> 5, d = idx & 31;
                const int gr = mT * 128 + hf * 64 + r;
                if (gr < NN) {
                    float4 v4 = *(float4*)&stg[r * 132 + 4 * d];
                    *(float4*)(out_v + (size_t)gr * 256 + d * 8 + (nt - 4) * 4) = v4;
                }
            }
        }
    }
}

// ---------------------------------------------------------------------------
// Pass 1: 4 edges/warp, 8 lanes/edge, contiguous 16B chunks per lane.
// ---------------------------------------------------------------------------
__global__ void __launch_bounds__(256) edge_pass1(
    const int* __restrict__ edge,
    const float* __restrict__ ew,
    float* __restrict__ out_att)
{
    const int lane = threadIdx.x & 31;
    const int wid = threadIdx.x >> 5;
    const int e = blockIdx.x * 32 + wid * 4 + (lane >> 3);
    const int l = lane & 7;

    const int src = __ldg(edge + e);
    const int dst = __ldg(edge + EE + e);
    const float w = __ldg(ew + e);

    const uint4* qb = (const uint4*)(g_q + (size_t)src * 256);
    const uint4* kb = (const uint4*)(g_k + (size_t)dst * 256);

    uint4 qv[4], kv[4];
#pragma unroll
    for (int i = 0; i < 4; i++) { qv[i] = qb[i * 8 + l]; kv[i] = kb[i * 8 + l]; }

    float pp[4];
#pragma unroll
    for (int i = 0; i < 4; i++) {
        const __half2* qh = (const __half2*)&qv[i];
        const __half2* kh = (const __half2*)&kv[i];
        __half2 hacc = __hmul2(qh[0], kh[0]);
        hacc = __hfma2(qh[1], kh[1], hacc);
        hacc = __hfma2(qh[2], kh[2], hacc);
        hacc = __hfma2(qh[3], kh[3], hacc);
        float2 f2 = __half22float2(hacc);
        float p = f2.x + f2.y;
        p += __shfl_xor_sync(0xffffffffu, p, 1);
        p += __shfl_xor_sync(0xffffffffu, p, 2);
        pp[i] = p;
    }

    const int i3 = l & 3;
    float v = pp[0];
    if (i3 == 1) v = pp[1];
    if (i3 == 2) v = pp[2];
    if (i3 == 3) v = pp[3];
    const int h = 2 * i3 + (l >> 2);

    const float ex = __expf(v * 0.17677669529663687f * w);   // 1/sqrt(32)
    out_att[(size_t)e * HH + h] = ex;
    atomicAdd(&g_sum[src * HH + h], ex);
}

// ---------------------------------------------------------------------------
// Pass 2: normalize.
// ---------------------------------------------------------------------------
__global__ void __launch_bounds__(256) edge_pass2(
    const int* __restrict__ edge,
    float* __restrict__ out_att)
{
    const int e = blockIdx.x * 256 + threadIdx.x;
    if (e >= EE) return;
    const int src = edge[e];

    const float4* sp = (const float4*)(g_sum + src * HH);
    float4 s0 = sp[0], s1 = sp[1];

    float4* ap = (float4*)(out_att + (size_t)e * HH);
    float4 a0 = ap[0], a1 = ap[1];

    a0.x = __fdividef(a0.x, s0.x + 1e-16f);
    a0.y = __fdividef(a0.y, s0.y + 1e-16f);
    a0.z = __fdividef(a0.z, s0.z + 1e-16f);
    a0.w = __fdividef(a0.w, s0.w + 1e-16f);
    a1.x = __fdividef(a1.x, s1.x + 1e-16f);
    a1.y = __fdividef(a1.y, s1.y + 1e-16f);
    a1.z = __fdividef(a1.z, s1.z + 1e-16f);
    a1.w = __fdividef(a1.w, s1.w + 1e-16f);

    ap[0] = a0; ap[1] = a1;
}

// ---------------------------------------------------------------------------
extern "C" void kernel_launch(void* const* d_in, const int* in_sizes, int n_in,
                              void* d_out, int out_size)
{
    const float* x    = (const float*)d_in[0];
    const int*   edge = (const int*)d_in[1];
    const float* ew   = (const float*)d_in[2];
    const float* Wq   = (const float*)d_in[3];
    const float* bq   = (const float*)d_in[4];
    const float* Wk   = (const float*)d_in[5];
    const float* bk   = (const float*)d_in[6];
    const float* Wv   = (const float*)d_in[7];
    const float* bv   = (const float*)d_in[8];

    float* out_att = (float*)d_out;
    float* out_v   = out_att + (size_t)EE * HH;

    static cudaStream_t s2 = nullptr;
    static cudaEvent_t evA = nullptr, evB = nullptr, evQK = nullptr, evJoin = nullptr;
    if (s2 == nullptr) {
        cudaStreamCreateWithFlags(&s2, cudaStreamNonBlocking);
        cudaEventCreateWithFlags(&evA, cudaEventDisableTiming);
        cudaEventCreateWithFlags(&evB, cudaEventDisableTiming);
        cudaEventCreateWithFlags(&evQK, cudaEventDisableTiming);
        cudaEventCreateWithFlags(&evJoin, cudaEventDisableTiming);
        cudaFuncSetAttribute(gemm_mma, cudaFuncAttributeMaxDynamicSharedMemorySize, SMEM_GEMM);
    }

    // conv_AW: x half A + W + zero sums (serial prefix)
    conv_AW<<<(XA_GROUPS + WGROUPS + ZGROUPS + 255) / 256, 256>>>(x, Wq, Wk, Wv);
    cudaEventRecord(evA, 0);

    // conv_B on s2: overlaps qk-GEMM half A
    cudaStreamWaitEvent(s2, evA, 0);
    conv_B<<<(XB_GROUPS + 255) / 256, 256, 0, s2>>>(x);
    cudaEventRecord(evB, s2);

    // qk-GEMM half A (rows < XSPLIT, converted)
    dim3 gqkA(4, MT_A);
    gemm_mma<<<gqkA, 256, SMEM_GEMM>>>(0, 0, bq, bk, bv, out_v);

    // qk-GEMM half B (needs conv_B)
    cudaStreamWaitEvent(0, evB, 0);
    dim3 gqkB(4, MT_B);
    gemm_mma<<<gqkB, 256, SMEM_GEMM>>>(0, MT_A, bq, bk, bv, out_v);
    cudaEventRecord(evQK, 0);

    // v-GEMM on s2 after qk: overlaps edge_pass1 (memory-bound)
    cudaStreamWaitEvent(s2, evQK, 0);
    dim3 gv(2, MT_ALL);
    gemm_mma<<<gv, 256, SMEM_GEMM, s2>>>(4, 0, bq, bk, bv, out_v);

    edge_pass1<<<EE / 32, 256>>>(edge, ew, out_att);

    edge_pass2<<<(EE + 255) / 256, 256>>>(edge, out_att);

    // join
    cudaEventRecord(evJoin, s2);
    cudaStreamWaitEvent(0, evJoin, 0);
}

// round 15
// speedup vs baseline: 1.1678x; 1.1678x over previous
#include <cuda_runtime.h>
#include <cuda_fp16.h>
#include <cstdint>

#define NN 50000
#define EE 800000
#define KF 256
#define HH 8
#define WROWS 768   // [Wq;Wk;Wv]

// ---------------------------------------------------------------------------
// Scratch (static device globals; no allocation anywhere)
// ---------------------------------------------------------------------------
__device__ __align__(16) __half g_q[(size_t)NN * 256];
__device__ __align__(16) __half g_k[(size_t)NN * 256];
__device__ __align__(16) float g_sum[NN * HH];
__device__ __align__(16) __half g_xh[(size_t)NN * KF];
__device__ __align__(16) __half g_wh[(size_t)WROWS * KF];

// ---------------------------------------------------------------------------
__device__ __forceinline__ uint32_t smem_u32(const void* p) {
    uint32_t a;
    asm("{ .reg .u64 t; cvta.to.shared.u64 t, %1; cvt.u32.u64 %0, t; }" : "=r"(a) : "l"(p));
    return a;
}
__device__ __forceinline__ void ldsm_x4(uint32_t* r, uint32_t addr) {
    asm volatile("ldmatrix.sync.aligned.m8n8.x4.shared.b16 {%0,%1,%2,%3}, [%4];"
                 : "=r"(r[0]), "=r"(r[1]), "=r"(r[2]), "=r"(r[3]) : "r"(addr));
}
__device__ __forceinline__ void mma_f16(float* c, const uint32_t* a, uint32_t b0, uint32_t b1) {
    asm volatile(
        "mma.sync.aligned.m16n8k16.row.col.f32.f16.f16.f32 "
        "{%0,%1,%2,%3}, {%4,%5,%6,%7}, {%8,%9}, {%0,%1,%2,%3};"
        : "+f"(c[0]), "+f"(c[1]), "+f"(c[2]), "+f"(c[3])
        : "r"(a[0]), "r"(a[1]), "r"(a[2]), "r"(a[3]), "r"(b0), "r"(b1));
}
__device__ __forceinline__ void cp_async16(uint32_t smem_addr, const void* gptr, uint32_t src_bytes) {
    asm volatile("cp.async.cg.shared.global [%0], [%1], 16, %2;"
                 :: "r"(smem_addr), "l"(gptr), "r"(src_bytes) : "memory");
}
#define CP_COMMIT() asm volatile("cp.async.commit_group;" ::: "memory")
#define CP_WAIT(n)  asm volatile("cp.async.wait_group %0;" :: "n"(n) : "memory")

// ---------------------------------------------------------------------------
// Convert pre-pass: x -> g_xh (fp16); W concat -> g_wh (fp16); zero g_sum.
// ---------------------------------------------------------------------------
#define XGROUPS (NN * KF / 4)          // 3,200,000
#define WGROUPS (WROWS * KF / 4)       // 49,152
#define ZGROUPS (NN * HH / 4)          // 100,000
__global__ void __launch_bounds__(256) convert_fp16(
    const float* __restrict__ x,
    const float* __restrict__ Wq, const float* __restrict__ Wk, const float* __restrict__ Wv)
{
    int idx = blockIdx.x * 256 + threadIdx.x;
    if (idx >= XGROUPS + WGROUPS) {
        int z = idx - (XGROUPS + WGROUPS);
        if (z < ZGROUPS)
            *(float4*)(g_sum + (size_t)z * 4) = make_float4(0.f, 0.f, 0.f, 0.f);
        return;
    }

    const float* src;
    __half* dst;
    size_t off;
    if (idx < XGROUPS) {
        src = x; off = (size_t)idx * 4;
        dst = g_xh;
    } else {
        int widx = idx - XGROUPS;
        off = (size_t)widx * 4;
        size_t row = off / KF;
        const float* Wm = (row < 256) ? Wq : (row < 512) ? Wk : Wv;
        src = Wm - ((row < 256) ? 0 : (row < 512) ? 256 * KF : 512 * KF);
        dst = g_wh;
    }
    float4 v = *(const float4*)(src + off);
    __half2 p0 = __floats2half2_rn(v.x, v.y);
    __half2 p1 = __floats2half2_rn(v.z, v.w);
    uint2 u;
    u.x = *(uint32_t*)&p0; u.y = *(uint32_t*)&p1;
    *(uint2*)(dst + off) = u;
}

// ---------------------------------------------------------------------------
// Pipelined mma.sync QKV GEMM (fp16): C[N,768] = x @ W^T + b
// nt = ntBase + blockIdx.x : 0-1 -> g_q | 2-3 -> g_k | 4-5 -> out_v (staged)
// BM=128, BN=128, BK=32; 8 warps; 5-stage cp.async pipeline (dist 4),
// ONE __syncthreads per slice. SMEM = 5*20480 = 102400.
// ---------------------------------------------------------------------------
#define NSTAGE 5
#define STAGE_BYTES 20480u   // A(128*40*2=10240) + B(10240)
#define B_OFF 10240u
#define SMEM_GEMM (NSTAGE * STAGE_BYTES)

extern __shared__ char dynsmem[];

__global__ void __launch_bounds__(256, 2) gemm_mma(
    int ntBase,
    const float* __restrict__ bq, const float* __restrict__ bk, const float* __restrict__ bv,
    float* __restrict__ out_v)
{
    const int t = threadIdx.x;
    const int wid = t >> 5;
    const int lane = t & 31;
    const int nt = ntBase + blockIdx.x;
    const int mT = blockIdx.y;      // 0..390
    const bool isV = (nt >= 4);

    const int wm = (wid >> 1) * 32;
    const int wn = (wid & 1) * 64;

    const uint32_t sb = smem_u32(dynsmem);

    const int rA = (lane & 15);
    const int cA = (lane >> 4) << 3;
    const int rB = (lane & 7) + ((lane >> 4) << 3);
    const int cB = ((lane >> 3) & 1) << 3;

    uint32_t addrA[2], addrB[4];
#pragma unroll
    for (int mi = 0; mi < 2; mi++)
        addrA[mi] = sb + (uint32_t)(wm + mi * 16 + rA) * 80u + (uint32_t)cA * 2u;
#pragma unroll
    for (int nf4 = 0; nf4 < 4; nf4++)
        addrB[nf4] = sb + B_OFF + (uint32_t)(wn + nf4 * 16 + rB) * 80u + (uint32_t)cB * 2u;

    float acc[2][8][4];
#pragma unroll
    for (int mi = 0; mi < 2; mi++)
#pragma unroll
        for (int nf = 0; nf < 8; nf++)
#pragma unroll
            for (int i = 0; i < 4; i++) acc[mi][nf][i] = 0.f;

    const int lrow = t >> 1;
    const int lcg = (t & 1) * 16;
    const int growL = mT * 128 + lrow;
    const uint32_t aBytes = (growL < NN) ? 16u : 0u;
    const int brow = nt * 128 + lrow;

    const uint32_t dstA0 = sb + (uint32_t)lrow * 80u + (uint32_t)lcg * 2u;
    const uint32_t dstB0 = sb + B_OFF + (uint32_t)lrow * 80u + (uint32_t)lcg * 2u;

    auto issue = [&](int s) {
        if (s < 8) {
            const uint32_t st = (uint32_t)(s % NSTAGE) * STAGE_BYTES;
            const __half* ap = g_xh + (size_t)growL * KF + s * 32 + lcg;
            const __half* bp = g_wh + (size_t)brow * KF + s * 32 + lcg;
            cp_async16(dstA0 + st, ap, aBytes);
            cp_async16(dstA0 + st + 16, ap + 8, aBytes);
            cp_async16(dstB0 + st, bp, 16u);
            cp_async16(dstB0 + st + 16, bp + 8, 16u);
        }
        CP_COMMIT();
    };

    issue(0); issue(1); issue(2); issue(3);
#pragma unroll
    for (int s = 0; s < 8; s++) {
        CP_WAIT(3);
        __syncthreads();
        issue(s + 4);

        const uint32_t st = (uint32_t)(s % NSTAGE) * STAGE_BYTES;
#pragma unroll
        for (int kk = 0; kk < 2; kk++) {
            uint32_t afrag[2][4];
            ldsm_x4(afrag[0], addrA[0] + st + kk * 32);
            ldsm_x4(afrag[1], addrA[1] + st + kk * 32);
            uint32_t bfrag[4][4];
#pragma unroll
            for (int nf4 = 0; nf4 < 4; nf4++)
                ldsm_x4(bfrag[nf4], addrB[nf4] + st + kk * 32);
#pragma unroll
            for (int mi = 0; mi < 2; mi++)
#pragma unroll
                for (int nf = 0; nf < 8; nf++)
                    mma_f16(acc[mi][nf], afrag[mi],
                            bfrag[nf >> 1][(nf & 1) * 2],
                            bfrag[nf >> 1][(nf & 1) * 2 + 1]);
        }
    }

    const int g = lane >> 2, tg = lane & 3;

    if (!isV) {
        // ---- q/k epilogue: hoisted biases, direct half2 stores ----
        const bool isQ = (nt < 2);
        const float* bptr = isQ ? bq : bk;
        __half* dst = isQ ? g_q : g_k;
        const int colBase = (nt & 1) * 128;
        float bb[8][2];
#pragma unroll
        for (int nf = 0; nf < 8; nf++) {
            const int lc = colBase + wn + nf * 8 + tg * 2;
            bb[nf][0] = __ldg(bptr + lc);
            bb[nf][1] = __ldg(bptr + lc + 1);
        }
#pragma unroll
        for (int mi = 0; mi < 2; mi++) {
            const int r0 = wm + mi * 16 + g;
#pragma unroll
            for (int hh = 0; hh < 2; hh++) {
                const int gr = mT * 128 + r0 + hh * 8;
                if (gr >= NN) continue;
#pragma unroll
                for (int nf = 0; nf < 8; nf++) {
                    const int lc = colBase + wn + nf * 8 + tg * 2;
                    float v0 = acc[mi][nf][hh * 2]     + bb[nf][0];
                    float v1 = acc[mi][nf][hh * 2 + 1] + bb[nf][1];
                    __half2 p2 = __floats2half2_rn(v0, v1);
                    *(__half2*)(dst + (size_t)gr * 256 + lc) = p2;
                }
            }
        }
    } else {
        // ---- v epilogue: stage 64-row halves in SMEM, coalesced float4 out ----
        float* stg = (float*)dynsmem;
        const int wcBase = (nt - 4) * 128;
        float bb[8][2];
#pragma unroll
        for (int nf = 0; nf < 8; nf++) {
            const int c0 = wn + nf * 8 + tg * 2;
            bb[nf][0] = __ldg(bv + wcBase + c0);
            bb[nf][1] = __ldg(bv + wcBase + c0 + 1);
        }
#pragma unroll
        for (int hf = 0; hf < 2; hf++) {
            __syncthreads();
            if ((wm >> 6) == hf) {
#pragma unroll
                for (int mi = 0; mi < 2; mi++) {
#pragma unroll
                    for (int hh = 0; hh < 2; hh++) {
                        const int lr = (wm & 63) + mi * 16 + g + hh * 8;
#pragma unroll
                        for (int nf = 0; nf < 8; nf++) {
                            const int c0 = wn + nf * 8 + tg * 2;
                            float v0 = acc[mi][nf][hh * 2]     + bb[nf][0];
                            float v1 = acc[mi][nf][hh * 2 + 1] + bb[nf][1];
                            stg[lr * 132 + 4 * (c0 & 31) + (c0 >> 5)] = v0;
                            stg[lr * 132 + 4 * ((c0 + 1) & 31) + ((c0 + 1) >> 5)] = v1;
                        }
                    }
                }
            }
            __syncthreads();
#pragma unroll
            for (int it = 0; it < 8; it++) {
                const int idx = it * 256 + t;
                const int r = idx >> 5, d = idx & 31;
                const int gr = mT * 128 + hf * 64 + r;
                if (gr < NN) {
                    float4 v4 = *(float4*)&stg[r * 132 + 4 * d];
                    *(float4*)(out_v + (size_t)gr * 256 + d * 8 + (nt - 4) * 4) = v4;
                }
            }
        }
    }
}

// ---------------------------------------------------------------------------
// Pass 1: 8 edges/warp, 8 lanes/edge-pair, 2 edges per lane (MLP=16).
// Lane l (0..7) of group g (0..3): edges e0=base+2g, e1=base+2g+1.
// Contiguous 16B chunks per lane; per-chunk half2 dot, fp32 promote;
// 2 xor-shuffle reduce; lane l stores head 2*(l&3)+(l>>2) for both edges.
// ---------------------------------------------------------------------------
__global__ void __launch_bounds__(256) edge_pass1(
    const int* __restrict__ edge,
    const float* __restrict__ ew,
    float* __restrict__ out_att)
{
    const int lane = threadIdx.x & 31;
    const int wid = threadIdx.x >> 5;
    const int g4 = lane >> 3;                     // 0..3
    const int e0 = blockIdx.x * 64 + wid * 8 + g4 * 2;
    const int e1 = e0 + 1;
    const int l = lane & 7;

    const int src0 = __ldg(edge + e0);
    const int dst0 = __ldg(edge + EE + e0);
    const int src1 = __ldg(edge + e1);
    const int dst1 = __ldg(edge + EE + e1);
    const float w0 = __ldg(ew + e0);
    const float w1 = __ldg(ew + e1);

    const uint4* qb0 = (const uint4*)(g_q + (size_t)src0 * 256);
    const uint4* kb0 = (const uint4*)(g_k + (size_t)dst0 * 256);
    const uint4* qb1 = (const uint4*)(g_q + (size_t)src1 * 256);
    const uint4* kb1 = (const uint4*)(g_k + (size_t)dst1 * 256);

    // front-batched: 16 independent LDG.128 per lane
    uint4 qv0[4], kv0[4], qv1[4], kv1[4];
#pragma unroll
    for (int i = 0; i < 4; i++) {
        qv0[i] = qb0[i * 8 + l]; kv0[i] = kb0[i * 8 + l];
        qv1[i] = qb1[i * 8 + l]; kv1[i] = kb1[i * 8 + l];
    }

    float pp0[4], pp1[4];
#pragma unroll
    for (int i = 0; i < 4; i++) {
        const __half2* qh0 = (const __half2*)&qv0[i];
        const __half2* kh0 = (const __half2*)&kv0[i];
        __half2 a0 = __hmul2(qh0[0], kh0[0]);
        a0 = __hfma2(qh0[1], kh0[1], a0);
        a0 = __hfma2(qh0[2], kh0[2], a0);
        a0 = __hfma2(qh0[3], kh0[3], a0);
        float2 f0 = __half22float2(a0);
        float p0 = f0.x + f0.y;

        const __half2* qh1 = (const __half2*)&qv1[i];
        const __half2* kh1 = (const __half2*)&kv1[i];
        __half2 a1 = __hmul2(qh1[0], kh1[0]);
        a1 = __hfma2(qh1[1], kh1[1], a1);
        a1 = __hfma2(qh1[2], kh1[2], a1);
        a1 = __hfma2(qh1[3], kh1[3], a1);
        float2 f1 = __half22float2(a1);
        float p1 = f1.x + f1.y;

        p0 += __shfl_xor_sync(0xffffffffu, p0, 1);
        p0 += __shfl_xor_sync(0xffffffffu, p0, 2);
        p1 += __shfl_xor_sync(0xffffffffu, p1, 1);
        p1 += __shfl_xor_sync(0xffffffffu, p1, 2);
        pp0[i] = p0;
        pp1[i] = p1;
    }

    const int i3 = l & 3;
    float v0 = pp0[0], v1 = pp1[0];
    if (i3 == 1) { v0 = pp0[1]; v1 = pp1[1]; }
    if (i3 == 2) { v0 = pp0[2]; v1 = pp1[2]; }
    if (i3 == 3) { v0 = pp0[3]; v1 = pp1[3]; }
    const int h = 2 * i3 + (l >> 2);

    const float ex0 = __expf(v0 * 0.17677669529663687f * w0);   // 1/sqrt(32)
    const float ex1 = __expf(v1 * 0.17677669529663687f * w1);
    out_att[(size_t)e0 * HH + h] = ex0;
    out_att[(size_t)e1 * HH + h] = ex1;
    atomicAdd(&g_sum[src0 * HH + h], ex0);
    atomicAdd(&g_sum[src1 * HH + h], ex1);
}

// ---------------------------------------------------------------------------
// Pass 2: normalize.
// ---------------------------------------------------------------------------
__global__ void __launch_bounds__(256) edge_pass2(
    const int* __restrict__ edge,
    float* __restrict__ out_att)
{
    const int e = blockIdx.x * 256 + threadIdx.x;
    if (e >= EE) return;
    const int src = edge[e];

    const float4* sp = (const float4*)(g_sum + src * HH);
    float4 s0 = sp[0], s1 = sp[1];

    float4* ap = (float4*)(out_att + (size_t)e * HH);
    float4 a0 = ap[0], a1 = ap[1];

    a0.x = __fdividef(a0.x, s0.x + 1e-16f);
    a0.y = __fdividef(a0.y, s0.y + 1e-16f);
    a0.z = __fdividef(a0.z, s0.z + 1e-16f);
    a0.w = __fdividef(a0.w, s0.w + 1e-16f);
    a1.x = __fdividef(a1.x, s1.x + 1e-16f);
    a1.y = __fdividef(a1.y, s1.y + 1e-16f);
    a1.z = __fdividef(a1.z, s1.z + 1e-16f);
    a1.w = __fdividef(a1.w, s1.w + 1e-16f);

    ap[0] = a0; ap[1] = a1;
}

// ---------------------------------------------------------------------------
extern "C" void kernel_launch(void* const* d_in, const int* in_sizes, int n_in,
                              void* d_out, int out_size)
{
    const float* x    = (const float*)d_in[0];
    const int*   edge = (const int*)d_in[1];
    const float* ew   = (const float*)d_in[2];
    const float* Wq   = (const float*)d_in[3];
    const float* bq   = (const float*)d_in[4];
    const float* Wk   = (const float*)d_in[5];
    const float* bk   = (const float*)d_in[6];
    const float* Wv   = (const float*)d_in[7];
    const float* bv   = (const float*)d_in[8];

    float* out_att = (float*)d_out;
    float* out_v   = out_att + (size_t)EE * HH;

    static cudaStream_t s2 = nullptr;
    static cudaEvent_t evFork = nullptr, evJoin = nullptr;
    if (s2 == nullptr) {
        cudaStreamCreateWithFlags(&s2, cudaStreamNonBlocking);
        cudaEventCreateWithFlags(&evFork, cudaEventDisableTiming);
        cudaEventCreateWithFlags(&evJoin, cudaEventDisableTiming);
        cudaFuncSetAttribute(gemm_mma, cudaFuncAttributeMaxDynamicSharedMemorySize, SMEM_GEMM);
    }

    convert_fp16<<<(XGROUPS + WGROUPS + ZGROUPS + 255) / 256, 256>>>(x, Wq, Wk, Wv);

    // fork: v-GEMM runs concurrently with qk-GEMM + edge passes (R13 schedule)
    cudaEventRecord(evFork, 0);
    cudaStreamWaitEvent(s2, evFork, 0);

    dim3 gv(2, (NN + 127) / 128);
    gemm_mma<<<gv, 256, SMEM_GEMM, s2>>>(4, bq, bk, bv, out_v);

    dim3 gqk(4, (NN + 127) / 128);
    gemm_mma<<<gqk, 256, SMEM_GEMM>>>(0, bq, bk, bv, out_v);

    edge_pass1<<<EE / 64, 256>>>(edge, ew, out_att);

    edge_pass2<<<(EE + 255) / 256, 256>>>(edge, out_att);

    // join
    cudaEventRecord(evJoin, s2);
    cudaStreamWaitEvent(0, evJoin, 0);
}

// round 16
// speedup vs baseline: 1.2087x; 1.0351x over previous
#include <cuda_runtime.h>
#include <cuda_fp16.h>
#include <cstdint>

#define NN 50000
#define EE 800000
#define KF 256
#define HH 8
#define WROWS 768   // [Wq;Wk;Wv]

// ---------------------------------------------------------------------------
// Scratch (static device globals; no allocation anywhere)
// ---------------------------------------------------------------------------
__device__ __align__(16) __half g_q[(size_t)NN * 256];
__device__ __align__(16) __half g_k[(size_t)NN * 256];
__device__ __align__(16) float g_sum[NN * HH];
__device__ __align__(16) __half g_xh[(size_t)NN * KF];
__device__ __align__(16) __half g_wh[(size_t)WROWS * KF];

// ---------------------------------------------------------------------------
__device__ __forceinline__ uint32_t smem_u32(const void* p) {
    uint32_t a;
    asm("{ .reg .u64 t; cvta.to.shared.u64 t, %1; cvt.u32.u64 %0, t; }" : "=r"(a) : "l"(p));
    return a;
}
__device__ __forceinline__ void ldsm_x4(uint32_t* r, uint32_t addr) {
    asm volatile("ldmatrix.sync.aligned.m8n8.x4.shared.b16 {%0,%1,%2,%3}, [%4];"
                 : "=r"(r[0]), "=r"(r[1]), "=r"(r[2]), "=r"(r[3]) : "r"(addr));
}
__device__ __forceinline__ void mma_f16(float* c, const uint32_t* a, uint32_t b0, uint32_t b1) {
    asm volatile(
        "mma.sync.aligned.m16n8k16.row.col.f32.f16.f16.f32 "
        "{%0,%1,%2,%3}, {%4,%5,%6,%7}, {%8,%9}, {%0,%1,%2,%3};"
        : "+f"(c[0]), "+f"(c[1]), "+f"(c[2]), "+f"(c[3])
        : "r"(a[0]), "r"(a[1]), "r"(a[2]), "r"(a[3]), "r"(b0), "r"(b1));
}
__device__ __forceinline__ void cp_async16(uint32_t smem_addr, const void* gptr, uint32_t src_bytes) {
    asm volatile("cp.async.cg.shared.global [%0], [%1], 16, %2;"
                 :: "r"(smem_addr), "l"(gptr), "r"(src_bytes) : "memory");
}
#define CP_COMMIT() asm volatile("cp.async.commit_group;" ::: "memory")
#define CP_WAIT(n)  asm volatile("cp.async.wait_group %0;" :: "n"(n) : "memory")

// ---------------------------------------------------------------------------
// Convert pre-pass: x -> g_xh (fp16); W concat -> g_wh (fp16); zero g_sum.
// ---------------------------------------------------------------------------
#define XGROUPS (NN * KF / 4)          // 3,200,000
#define WGROUPS (WROWS * KF / 4)       // 49,152
#define ZGROUPS (NN * HH / 4)          // 100,000
__global__ void __launch_bounds__(256) convert_fp16(
    const float* __restrict__ x,
    const float* __restrict__ Wq, const float* __restrict__ Wk, const float* __restrict__ Wv)
{
    int idx = blockIdx.x * 256 + threadIdx.x;
    if (idx >= XGROUPS + WGROUPS) {
        int z = idx - (XGROUPS + WGROUPS);
        if (z < ZGROUPS)
            *(float4*)(g_sum + (size_t)z * 4) = make_float4(0.f, 0.f, 0.f, 0.f);
        return;
    }

    const float* src;
    __half* dst;
    size_t off;
    if (idx < XGROUPS) {
        src = x; off = (size_t)idx * 4;
        dst = g_xh;
    } else {
        int widx = idx - XGROUPS;
        off = (size_t)widx * 4;
        size_t row = off / KF;
        const float* Wm = (row < 256) ? Wq : (row < 512) ? Wk : Wv;
        src = Wm - ((row < 256) ? 0 : (row < 512) ? 256 * KF : 512 * KF);
        dst = g_wh;
    }
    float4 v = __ldcs((const float4*)(src + off));
    __half2 p0 = __floats2half2_rn(v.x, v.y);
    __half2 p1 = __floats2half2_rn(v.z, v.w);
    uint2 u;
    u.x = *(uint32_t*)&p0; u.y = *(uint32_t*)&p1;
    *(uint2*)(dst + off) = u;
}

// ---------------------------------------------------------------------------
// Pipelined mma.sync QKV GEMM (fp16): C[N,768] = x @ W^T + b
// nt = ntBase + blockIdx.x : 0-1 -> g_q | 2-3 -> g_k | 4-5 -> out_v (staged)
// BM=128, BN=128, BK=32; 8 warps; 5-stage cp.async pipeline (dist 4),
// ONE __syncthreads per slice. SMEM = 5*20480 = 102400.
// ---------------------------------------------------------------------------
#define NSTAGE 5
#define STAGE_BYTES 20480u   // A(128*40*2=10240) + B(10240)
#define B_OFF 10240u
#define SMEM_GEMM (NSTAGE * STAGE_BYTES)

extern __shared__ char dynsmem[];

__global__ void __launch_bounds__(256, 2) gemm_mma(
    int ntBase,
    const float* __restrict__ bq, const float* __restrict__ bk, const float* __restrict__ bv,
    float* __restrict__ out_v)
{
    const int t = threadIdx.x;
    const int wid = t >> 5;
    const int lane = t & 31;
    const int nt = ntBase + blockIdx.x;
    const int mT = blockIdx.y;      // 0..390
    const bool isV = (nt >= 4);

    const int wm = (wid >> 1) * 32;
    const int wn = (wid & 1) * 64;

    const uint32_t sb = smem_u32(dynsmem);

    const int rA = (lane & 15);
    const int cA = (lane >> 4) << 3;
    const int rB = (lane & 7) + ((lane >> 4) << 3);
    const int cB = ((lane >> 3) & 1) << 3;

    uint32_t addrA[2], addrB[4];
#pragma unroll
    for (int mi = 0; mi < 2; mi++)
        addrA[mi] = sb + (uint32_t)(wm + mi * 16 + rA) * 80u + (uint32_t)cA * 2u;
#pragma unroll
    for (int nf4 = 0; nf4 < 4; nf4++)
        addrB[nf4] = sb + B_OFF + (uint32_t)(wn + nf4 * 16 + rB) * 80u + (uint32_t)cB * 2u;

    float acc[2][8][4];
#pragma unroll
    for (int mi = 0; mi < 2; mi++)
#pragma unroll
        for (int nf = 0; nf < 8; nf++)
#pragma unroll
            for (int i = 0; i < 4; i++) acc[mi][nf][i] = 0.f;

    const int lrow = t >> 1;
    const int lcg = (t & 1) * 16;
    const int growL = mT * 128 + lrow;
    const uint32_t aBytes = (growL < NN) ? 16u : 0u;
    const int brow = nt * 128 + lrow;

    const uint32_t dstA0 = sb + (uint32_t)lrow * 80u + (uint32_t)lcg * 2u;
    const uint32_t dstB0 = sb + B_OFF + (uint32_t)lrow * 80u + (uint32_t)lcg * 2u;

    auto issue = [&](int s) {
        if (s < 8) {
            const uint32_t st = (uint32_t)(s % NSTAGE) * STAGE_BYTES;
            const __half* ap = g_xh + (size_t)growL * KF + s * 32 + lcg;
            const __half* bp = g_wh + (size_t)brow * KF + s * 32 + lcg;
            cp_async16(dstA0 + st, ap, aBytes);
            cp_async16(dstA0 + st + 16, ap + 8, aBytes);
            cp_async16(dstB0 + st, bp, 16u);
            cp_async16(dstB0 + st + 16, bp + 8, 16u);
        }
        CP_COMMIT();
    };

    issue(0); issue(1); issue(2); issue(3);
#pragma unroll
    for (int s = 0; s < 8; s++) {
        CP_WAIT(3);
        __syncthreads();
        issue(s + 4);

        const uint32_t st = (uint32_t)(s % NSTAGE) * STAGE_BYTES;
#pragma unroll
        for (int kk = 0; kk < 2; kk++) {
            uint32_t afrag[2][4];
            ldsm_x4(afrag[0], addrA[0] + st + kk * 32);
            ldsm_x4(afrag[1], addrA[1] + st + kk * 32);
            uint32_t bfrag[4][4];
#pragma unroll
            for (int nf4 = 0; nf4 < 4; nf4++)
                ldsm_x4(bfrag[nf4], addrB[nf4] + st + kk * 32);
#pragma unroll
            for (int mi = 0; mi < 2; mi++)
#pragma unroll
                for (int nf = 0; nf < 8; nf++)
                    mma_f16(acc[mi][nf], afrag[mi],
                            bfrag[nf >> 1][(nf & 1) * 2],
                            bfrag[nf >> 1][(nf & 1) * 2 + 1]);
        }
    }

    const int g = lane >> 2, tg = lane & 3;

    if (!isV) {
        // ---- q/k epilogue: hoisted biases, direct half2 stores ----
        const bool isQ = (nt < 2);
        const float* bptr = isQ ? bq : bk;
        __half* dst = isQ ? g_q : g_k;
        const int colBase = (nt & 1) * 128;
        float bb[8][2];
#pragma unroll
        for (int nf = 0; nf < 8; nf++) {
            const int lc = colBase + wn + nf * 8 + tg * 2;
            bb[nf][0] = __ldg(bptr + lc);
            bb[nf][1] = __ldg(bptr + lc + 1);
        }
#pragma unroll
        for (int mi = 0; mi < 2; mi++) {
            const int r0 = wm + mi * 16 + g;
#pragma unroll
            for (int hh = 0; hh < 2; hh++) {
                const int gr = mT * 128 + r0 + hh * 8;
                if (gr >= NN) continue;
#pragma unroll
                for (int nf = 0; nf < 8; nf++) {
                    const int lc = colBase + wn + nf * 8 + tg * 2;
                    float v0 = acc[mi][nf][hh * 2]     + bb[nf][0];
                    float v1 = acc[mi][nf][hh * 2 + 1] + bb[nf][1];
                    __half2 p2 = __floats2half2_rn(v0, v1);
                    *(__half2*)(dst + (size_t)gr * 256 + lc) = p2;
                }
            }
        }
    } else {
        // ---- v epilogue: stage 64-row halves in SMEM, coalesced float4 out ----
        float* stg = (float*)dynsmem;
        const int wcBase = (nt - 4) * 128;
        float bb[8][2];
#pragma unroll
        for (int nf = 0; nf < 8; nf++) {
            const int c0 = wn + nf * 8 + tg * 2;
            bb[nf][0] = __ldg(bv + wcBase + c0);
            bb[nf][1] = __ldg(bv + wcBase + c0 + 1);
        }
#pragma unroll
        for (int hf = 0; hf < 2; hf++) {
            __syncthreads();
            if ((wm >> 6) == hf) {
#pragma unroll
                for (int mi = 0; mi < 2; mi++) {
#pragma unroll
                    for (int hh = 0; hh < 2; hh++) {
                        const int lr = (wm & 63) + mi * 16 + g + hh * 8;
#pragma unroll
                        for (int nf = 0; nf < 8; nf++) {
                            const int c0 = wn + nf * 8 + tg * 2;
                            float v0 = acc[mi][nf][hh * 2]     + bb[nf][0];
                            float v1 = acc[mi][nf][hh * 2 + 1] + bb[nf][1];
                            stg[lr * 132 + 4 * (c0 & 31) + (c0 >> 5)] = v0;
                            stg[lr * 132 + 4 * ((c0 + 1) & 31) + ((c0 + 1) >> 5)] = v1;
                        }
                    }
                }
            }
            __syncthreads();
#pragma unroll
            for (int it = 0; it < 8; it++) {
                const int idx = it * 256 + t;
                const int r = idx >> 5, d = idx & 31;
                const int gr = mT * 128 + hf * 64 + r;
                if (gr < NN) {
                    float4 v4 = *(float4*)&stg[r * 132 + 4 * d];
                    __stcs((float4*)(out_v + (size_t)gr * 256 + d * 8 + (nt - 4) * 4), v4);
                }
            }
        }
    }
}

// ---------------------------------------------------------------------------
// Pass 1: 4 edges/warp, 8 lanes/edge, contiguous 16B chunks per lane.
// Streaming data (edge/ew) uses __ldcs so reused q/k rows keep L2 residency.
// ---------------------------------------------------------------------------
__global__ void __launch_bounds__(256) edge_pass1(
    const int* __restrict__ edge,
    const float* __restrict__ ew,
    float* __restrict__ out_att)
{
    const int lane = threadIdx.x & 31;
    const int wid = threadIdx.x >> 5;
    const int e = blockIdx.x * 32 + wid * 4 + (lane >> 3);
    const int l = lane & 7;

    const int src = __ldcs(edge + e);
    const int dst = __ldcs(edge + EE + e);
    const float w = __ldcs(ew + e);

    const uint4* qb = (const uint4*)(g_q + (size_t)src * 256);
    const uint4* kb = (const uint4*)(g_k + (size_t)dst * 256);

    uint4 qv[4], kv[4];
#pragma unroll
    for (int i = 0; i < 4; i++) { qv[i] = qb[i * 8 + l]; kv[i] = kb[i * 8 + l]; }

    float pp[4];
#pragma unroll
    for (int i = 0; i < 4; i++) {
        const __half2* qh = (const __half2*)&qv[i];
        const __half2* kh = (const __half2*)&kv[i];
        __half2 hacc = __hmul2(qh[0], kh[0]);
        hacc = __hfma2(qh[1], kh[1], hacc);
        hacc = __hfma2(qh[2], kh[2], hacc);
        hacc = __hfma2(qh[3], kh[3], hacc);
        float2 f2 = __half22float2(hacc);
        float p = f2.x + f2.y;
        p += __shfl_xor_sync(0xffffffffu, p, 1);
        p += __shfl_xor_sync(0xffffffffu, p, 2);
        pp[i] = p;
    }

    const int i3 = l & 3;
    float v = pp[0];
    if (i3 == 1) v = pp[1];
    if (i3 == 2) v = pp[2];
    if (i3 == 3) v = pp[3];
    const int h = 2 * i3 + (l >> 2);

    const float ex = __expf(v * 0.17677669529663687f * w);   // 1/sqrt(32)
    __stcs(out_att + (size_t)e * HH + h, ex);
    atomicAdd(&g_sum[src * HH + h], ex);
}

// ---------------------------------------------------------------------------
// Pass 2: normalize. Streaming RMW uses evict-first hints.
// ---------------------------------------------------------------------------
__global__ void __launch_bounds__(256) edge_pass2(
    const int* __restrict__ edge,
    float* __restrict__ out_att)
{
    const int e = blockIdx.x * 256 + threadIdx.x;
    if (e >= EE) return;
    const int src = __ldcs(edge + e);

    const float4* sp = (const float4*)(g_sum + src * HH);
    float4 s0 = sp[0], s1 = sp[1];

    float4* ap = (float4*)(out_att + (size_t)e * HH);
    float4 a0 = __ldcs(ap), a1 = __ldcs(ap + 1);

    a0.x = __fdividef(a0.x, s0.x + 1e-16f);
    a0.y = __fdividef(a0.y, s0.y + 1e-16f);
    a0.z = __fdividef(a0.z, s0.z + 1e-16f);
    a0.w = __fdividef(a0.w, s0.w + 1e-16f);
    a1.x = __fdividef(a1.x, s1.x + 1e-16f);
    a1.y = __fdividef(a1.y, s1.y + 1e-16f);
    a1.z = __fdividef(a1.z, s1.z + 1e-16f);
    a1.w = __fdividef(a1.w, s1.w + 1e-16f);

    __stcs(ap, a0);
    __stcs(ap + 1, a1);
}

// ---------------------------------------------------------------------------
extern "C" void kernel_launch(void* const* d_in, const int* in_sizes, int n_in,
                              void* d_out, int out_size)
{
    const float* x    = (const float*)d_in[0];
    const int*   edge = (const int*)d_in[1];
    const float* ew   = (const float*)d_in[2];
    const float* Wq   = (const float*)d_in[3];
    const float* bq   = (const float*)d_in[4];
    const float* Wk   = (const float*)d_in[5];
    const float* bk   = (const float*)d_in[6];
    const float* Wv   = (const float*)d_in[7];
    const float* bv   = (const float*)d_in[8];

    float* out_att = (float*)d_out;
    float* out_v   = out_att + (size_t)EE * HH;

    static cudaStream_t s2 = nullptr;
    static cudaEvent_t evFork = nullptr, evJoin = nullptr;
    if (s2 == nullptr) {
        cudaStreamCreateWithFlags(&s2, cudaStreamNonBlocking);
        cudaEventCreateWithFlags(&evFork, cudaEventDisableTiming);
        cudaEventCreateWithFlags(&evJoin, cudaEventDisableTiming);
        cudaFuncSetAttribute(gemm_mma, cudaFuncAttributeMaxDynamicSharedMemorySize, SMEM_GEMM);
    }

    convert_fp16<<<(XGROUPS + WGROUPS + ZGROUPS + 255) / 256, 256>>>(x, Wq, Wk, Wv);

    // fork: v-GEMM runs concurrently with qk-GEMM + edge passes (R13 schedule)
    cudaEventRecord(evFork, 0);
    cudaStreamWaitEvent(s2, evFork, 0);

    dim3 gv(2, (NN + 127) / 128);
    gemm_mma<<<gv, 256, SMEM_GEMM, s2>>>(4, bq, bk, bv, out_v);

    dim3 gqk(4, (NN + 127) / 128);
    gemm_mma<<<gqk, 256, SMEM_GEMM>>>(0, bq, bk, bv, out_v);

    edge_pass1<<<EE / 32, 256>>>(edge, ew, out_att);

    edge_pass2<<<(EE + 255) / 256, 256>>>(edge, out_att);

    // join
    cudaEventRecord(evJoin, s2);
    cudaStreamWaitEvent(0, evJoin, 0);
}